// round 16
// baseline (speedup 1.0000x reference)
#include <cuda_runtime.h>
#include <cuda_fp16.h>
#include <math.h>
#include <stdint.h>

#define BB 16
#define CC 512
#define L0 80000
#define L1 16000
#define L2 4000
#define L3 2000
#define L4 1000
#define L5 500
#define TT 500
#define HID 256
#define KCPC 12

__device__ float g_c1[BB*CC*L1];
__device__ float g_c2[BB*CC*L2];
__device__ float g_c3[BB*CC*L3];
__device__ float g_c4[BB*CC*L4];
__device__ float g_c5[BB*CC*L5];
__device__ float g_scale[5*CC];
__device__ float g_shift[5*CC];
__device__ uint32_t g_w2b[1310720];
__device__ uint32_t g_w345b[3*655360];
__device__ uint32_t g_apb[(size_t)BB*CC*8200];
__device__ float g_z[TT*BB*CC];
__device__ float g_gi[TT*BB*768];
__device__ float g_hbuf[2][BB*HID];
__device__ float g_ct[BB*HID];
__device__ float g_enc[KCPC*BB*CC];
__device__ float g_pred[KCPC*BB*CC];
__device__ float g_total[KCPC*BB*BB];
// barrier state: each on its OWN 128B line
__device__ __align__(128) unsigned g_bar_cnt[32];
__device__ __align__(128) unsigned g_epoch[32];
__device__ __align__(128) unsigned g_dbar[32];
__device__ __align__(128) unsigned g_depoch[32];

__device__ __forceinline__ uint32_t smem_to_u32(const void* p) {
    uint32_t a;
    asm("{ .reg .u64 t; cvta.to.shared.u64 t, %1; cvt.u32.u64 %0, t; }" : "=r"(a) : "l"(p));
    return a;
}
__device__ __forceinline__ uint32_t pack_h2(float v0, float v1) {
    __half2 h = __floats2half2_rn(v0, v1);
    return *(uint32_t*)&h;
}
__device__ __forceinline__ void mma_fp16(float* d, const uint32_t* a, const uint32_t* bfr) {
    asm volatile(
        "mma.sync.aligned.m16n8k16.row.col.f32.f16.f16.f32 "
        "{%0,%1,%2,%3}, {%4,%5,%6,%7}, {%8,%9}, {%0,%1,%2,%3};"
        : "+f"(d[0]), "+f"(d[1]), "+f"(d[2]), "+f"(d[3])
        : "r"(a[0]), "r"(a[1]), "r"(a[2]), "r"(a[3]), "r"(bfr[0]), "r"(bfr[1]));
}
#define MBARRIER_INIT(addr, cnt) \
    asm volatile("mbarrier.init.shared.b64 [%0], %1;" :: "r"((uint32_t)(addr)), "r"((uint32_t)(cnt)) : "memory")
#define MBARRIER_EXPECT_TX(addr, bytes) \
    asm volatile("mbarrier.arrive.expect_tx.shared.b64 _, [%0], %1;" :: "r"((uint32_t)(addr)), "r"((uint32_t)(bytes)) : "memory")
#define MBARRIER_WAIT_PARITY(addr, par) do { \
    uint32_t _m = (uint32_t)(addr); uint32_t _p = (uint32_t)(par); uint32_t _d; \
    asm volatile("{\n\t.reg .pred p;\n\tmbarrier.try_wait.parity.shared.b64 p, [%1], %2;\n\tselp.b32 %0, 1, 0, p;\n\t}" \
        : "=r"(_d) : "r"(_m), "r"(_p) : "memory"); \
    if (!_d) { \
        asm volatile("{\n\t.reg .pred P1;\n\tWL_%=:\n\tmbarrier.try_wait.parity.shared.b64 P1, [%0], %1;\n\t@P1 bra.uni WD_%=;\n\tbra.uni WL_%=;\n\tWD_%=:\n\t}" \
            :: "r"(_m), "r"(_p) : "memory"); \
    } \
} while (0)
#define BULK_G2S(dst, src, bytes, mb) \
    asm volatile("cp.async.bulk.shared::cluster.global.mbarrier::complete_tx::bytes [%0], [%1], %2, [%3];" \
        :: "r"((uint32_t)(dst)), "l"(src), "r"((uint32_t)(bytes)), "r"((uint32_t)(mb)) : "memory")

__global__ void init_kernel(const float* __restrict__ hidden) {
    if (blockIdx.x == 0 && threadIdx.x == 0) { g_bar_cnt[0] = 0u; g_epoch[0] = 0u; }
    int i = blockIdx.x * blockDim.x + threadIdx.x;
    if (i < BB*HID) g_hbuf[0][i] = hidden[i];
}
__global__ void reset_dummy_kernel() {
    g_dbar[0] = 0u; g_depoch[0] = 0u;
}

template<int KTOT>
__global__ void prepw_kernel(const float* __restrict__ w, uint32_t* __restrict__ wb) {
    int i = blockIdx.x*256 + threadIdx.x;
    if (i >= 512*(KTOT/2)) return;
    int co = i / (KTOT/2), wp = i % (KTOT/2);
    int chunk = wp >> 5, word = wp & 31;
    size_t d = (((size_t)chunk*4 + (co>>7))*128 + (co&127))*40 + word;
    wb[d] = pack_h2(w[(size_t)co*KTOT + 2*wp], w[(size_t)co*KTOT + 2*wp + 1]);
}

template<int LIN, int LPW, int SH>
__global__ void statsprep_kernel(const float* __restrict__ raw, const float* __restrict__ gamma,
                                 const float* __restrict__ beta, float* __restrict__ scale,
                                 float* __restrict__ shift) {
    int c = blockIdx.x, tid = threadIdx.x;
    double s = 0.0, s2 = 0.0;
    for (int b = 0; b < BB; b++) {
        const float* p = raw + (size_t)(b*CC + c)*LIN;
        for (int l = tid; l < LIN; l += 256) { float v = p[l]; s += v; s2 += (double)v*v; }
    }
    __shared__ double rs[256], rs2[256];
    __shared__ float sc_s, sh_s;
    rs[tid] = s; rs2[tid] = s2; __syncthreads();
    for (int st = 128; st > 0; st >>= 1) {
        if (tid < st) { rs[tid] += rs[tid+st]; rs2[tid] += rs2[tid+st]; }
        __syncthreads();
    }
    if (tid == 0) {
        double n = (double)BB * (double)LIN;
        double mean = rs[0]/n, var = rs2[0]/n - mean*mean;
        double scd = (double)gamma[c] / sqrt(var + 1e-5);
        float scf = (float)scd;
        float shf = (float)((double)beta[c] - mean*scd);
        scale[c] = scf; shift[c] = shf;
        sc_s = scf; sh_s = shf;
    }
    __syncthreads();
    float scf = sc_s, shf = sh_s;
    for (int b = 0; b < BB; b++) {
        const float* src = raw + (size_t)(b*CC + c)*LIN;
        uint32_t* db = g_apb + ((size_t)(b*CC) + c)*LPW;
        for (int w = tid; w < LPW; w += 256) {
            int p0 = 2*w - SH;
            float v0 = (p0 >= 0 && p0 < LIN) ? fmaxf(fmaf(src[p0], scf, shf), 0.f) : 0.f;
            float v1 = (p0+1 >= 0 && p0+1 < LIN) ? fmaxf(fmaf(src[p0+1], scf, shf), 0.f) : 0.f;
            db[w] = pack_h2(v0, v1);
        }
    }
}

__global__ void conv1_kernel(const float* __restrict__ x, const float* __restrict__ w) {
    __shared__ float wsm[CC*10];
    __shared__ float xs[256*5 + 10];
    int b = blockIdx.y, o0 = blockIdx.x * 256, tid = threadIdx.x;
    for (int i = tid; i < CC*10; i += 256) wsm[i] = w[i];
    int p0 = o0*5 - 3;
    for (int i = tid; i < 256*5 + 10; i += 256) {
        int p = p0 + i;
        xs[i] = (p >= 0 && p < L0) ? x[b*L0 + p] : 0.f;
    }
    __syncthreads();
    int o = o0 + tid;
    if (o >= L1) return;
    float xr[10];
#pragma unroll
    for (int j = 0; j < 10; j++) xr[j] = xs[tid*5 + j];
    for (int co = 0; co < CC; co++) {
        float acc = 0.f;
#pragma unroll
        for (int j = 0; j < 10; j++) acc = fmaf(wsm[co*10 + j], xr[j], acc);
        g_c1[(b*CC + co)*L1 + o] = acc;
    }
}

__global__ void stats_kernel(const float* __restrict__ raw, const float* __restrict__ gamma,
                             const float* __restrict__ beta, float* __restrict__ scale,
                             float* __restrict__ shift, int L) {
    int c = blockIdx.x, tid = threadIdx.x;
    double s = 0.0, s2 = 0.0;
    for (int b = 0; b < BB; b++) {
        const float* p = raw + (size_t)(b*CC + c)*L;
        for (int l = tid; l < L; l += 256) { float v = p[l]; s += v; s2 += (double)v*v; }
    }
    __shared__ double rs[256], rs2[256];
    rs[tid] = s; rs2[tid] = s2; __syncthreads();
    for (int st = 128; st > 0; st >>= 1) {
        if (tid < st) { rs[tid] += rs[tid+st]; rs2[tid] += rs2[tid+st]; }
        __syncthreads();
    }
    if (tid == 0) {
        double n = (double)BB * (double)L;
        double mean = rs[0]/n, var = rs2[0]/n - mean*mean;
        double sc = (double)gamma[c] / sqrt(var + 1e-5);
        scale[c] = (float)sc;
        shift[c] = (float)((double)beta[c] - mean*sc);
    }
}

template<int KW, int S, int KTOT, int LPW, int NW>
__global__ void __launch_bounds__(256, 2)
conv_tc_kernel(const uint32_t* __restrict__ pb, const uint32_t* __restrict__ wb,
               float* __restrict__ out, int Lout) {
    constexpr int CI = 64/KW, NC = KTOT/64;
    constexpr int AW = 5120;
    constexpr int BSTW = CI*NW;
    constexpr int STGW = AW + BSTW;
    constexpr int HDR = 32;
    extern __shared__ __align__(128) uint32_t smw[];
    uint32_t sbase = smem_to_u32(smw);
    int tid = threadIdx.x, wid = tid >> 5, lane = tid & 31;
    int g = lane >> 2, tig = lane & 3;
    int warp_m = wid >> 1, warp_n = wid & 1;
    int n0 = blockIdx.x*128, b = blockIdx.z;
    uint32_t txb = (uint32_t)(20480 + CI*NW*4);

    if (tid == 0) { MBARRIER_INIT(sbase, 1); MBARRIER_INIT(sbase + 8, 1); MBARRIER_INIT(sbase + 16, 1); }
    __syncthreads();
    asm volatile("fence.proxy.async;" ::: "memory");

    auto issue = [&](int c, int s) {
        uint32_t mb = sbase + s*8;
        uint32_t ast = sbase + (uint32_t)(HDR + s*STGW)*4;
        uint32_t bst = ast + AW*4;
        MBARRIER_EXPECT_TX(mb, txb);
        size_t aoff = ((size_t)c*4 + blockIdx.y)*AW;
        BULK_G2S(ast, wb + aoff, 20480, mb);
        int base = n0*(S/2);
        for (int r = 0; r < CI; r++) {
            size_t so = ((size_t)(b*CC) + (size_t)c*CI + r)*LPW + base;
            BULK_G2S(bst + (uint32_t)(r*NW)*4, pb + so, NW*4, mb);
        }
    };
    if (tid == 0) { issue(0, 0); issue(1, 1); if (NC > 2) issue(2, 2); }

    float acc[2][8][4];
#pragma unroll
    for (int mt = 0; mt < 2; mt++)
#pragma unroll
        for (int nt = 0; nt < 8; nt++)
#pragma unroll
            for (int q = 0; q < 4; q++) acc[mt][nt][q] = 0.f;

    int ph[3] = {0, 0, 0};
    int s = 0;
    for (int c = 0; c < NC; c++) {
        MBARRIER_WAIT_PARITY(sbase + s*8, ph[s]); ph[s] ^= 1;
        int Ab = HDR + s*STGW;
        int Bb = Ab + AW;
#pragma unroll
        for (int ks = 0; ks < 4; ks++) {
            int kw = ks*8;
            uint32_t ab[2][4];
#pragma unroll
            for (int mt = 0; mt < 2; mt++) {
                int r = warp_m*32 + mt*16 + g;
                ab[mt][0] = smw[Ab + r*40 + kw + tig];
                ab[mt][1] = smw[Ab + (r+8)*40 + kw + tig];
                ab[mt][2] = smw[Ab + r*40 + kw + tig + 4];
                ab[mt][3] = smw[Ab + (r+8)*40 + kw + tig + 4];
            }
#pragma unroll
            for (int nt = 0; nt < 8; nt++) {
                int nl = warp_n*64 + nt*8 + g;
                uint32_t bbf[2];
#pragma unroll
                for (int j = 0; j < 2; j++) {
                    int kk = ks*16 + 8*j + 2*tig;
                    int cil = kk / KW, jj = kk - cil*KW;
                    bbf[j] = smw[Bb + cil*NW + nl*(S/2) + (jj >> 1)];
                }
#pragma unroll
                for (int mt = 0; mt < 2; mt++)
                    mma_fp16(acc[mt][nt], ab[mt], bbf);
            }
        }
        __syncthreads();
        if (tid == 0 && c + 3 < NC) issue(c + 3, s);
        s = (s == 2) ? 0 : s + 1;
    }

#pragma unroll
    for (int mt = 0; mt < 2; mt++) {
        int co0 = blockIdx.y*128 + warp_m*32 + mt*16 + g;
#pragma unroll
        for (int nt = 0; nt < 8; nt++) {
            int n = n0 + warp_n*64 + nt*8 + 2*tig;
            if (n < Lout) {
                *(float2*)&out[(size_t)(b*CC + co0)*Lout + n]     = make_float2(acc[mt][nt][0], acc[mt][nt][1]);
                *(float2*)&out[(size_t)(b*CC + co0 + 8)*Lout + n] = make_float2(acc[mt][nt][2], acc[mt][nt][3]);
            }
        }
    }
}

__global__ void buildz_kernel(const int* __restrict__ ts, const float* __restrict__ sc,
                              const float* __restrict__ sh) {
    int t = blockIdx.x, b = blockIdx.y, d = threadIdx.x;
    float v = 0.f;
    if (t <= ts[b]) {
        float r = g_c5[(b*CC + d)*L5 + t];
        v = fmaxf(fmaf(r, sc[d], sh[d]), 0.f);
    }
    g_z[(t*BB + b)*CC + d] = v;
}

__global__ void gi_gemm_kernel(const float* __restrict__ wih) {
    __shared__ float As[16*65];
    __shared__ float Bs[16*65];
    int tid = threadIdx.x, tx = tid & 15, ty = tid >> 4;
    int r0 = blockIdx.x * 64, g0 = blockIdx.y * 64;
    float acc[4][4] = {};
    for (int k0 = 0; k0 < CC; k0 += 16) {
        for (int i = tid; i < 1024; i += 256) {
            int rl = i >> 4, kk = i & 15;
            As[kk*65 + rl] = g_z[(r0+rl)*CC + k0 + kk];
            Bs[kk*65 + rl] = wih[(g0+rl)*CC + k0 + kk];
        }
        __syncthreads();
#pragma unroll
        for (int kk = 0; kk < 16; kk++) {
            float av[4], bv[4];
#pragma unroll
            for (int i = 0; i < 4; i++) av[i] = As[kk*65 + ty*4 + i];
#pragma unroll
            for (int j = 0; j < 4; j++) bv[j] = Bs[kk*65 + tx*4 + j];
#pragma unroll
            for (int i = 0; i < 4; i++)
#pragma unroll
                for (int j = 0; j < 4; j++)
                    acc[i][j] = fmaf(av[i], bv[j], acc[i][j]);
        }
        __syncthreads();
    }
#pragma unroll
    for (int i = 0; i < 4; i++)
#pragma unroll
        for (int j = 0; j < 4; j++)
            g_gi[(r0 + ty*4 + i)*768 + g0 + tx*4 + j] = acc[i][j];
}

template<int NSTEP>
__global__ void gru_kernel(const float* __restrict__ whh, const float* __restrict__ bih,
                           const float* __restrict__ bhh, const int* __restrict__ ts,
                           unsigned* barcnt, unsigned* epoch) {
    __shared__ float ws[3*8*256];
    __shared__ float h_s[BB*HID];
    __shared__ float part[BB*8*2*3];
    __shared__ float bih_s[24], bhh_s[24];
    __shared__ int ts_s[BB];
    int tid = threadIdx.x, j0 = blockIdx.x * 8;
    int b = tid >> 4, jl = (tid >> 1) & 7, half = tid & 1;
    for (int i = tid; i < 6144; i += 256) {
        int g = i >> 11, rest = i & 2047, jj = rest >> 8, k = rest & 255;
        ws[i] = whh[(g*256 + j0 + jj)*256 + k];
    }
    if (tid < 24) {
        int g = tid / 8, jj = tid % 8;
        bih_s[tid] = bih[g*256 + j0 + jj];
        bhh_s[tid] = bhh[g*256 + j0 + jj];
    }
    if (tid < BB) ts_s[tid] = ts[tid];
    __syncthreads();
    for (int t = 0; t < NSTEP; t++) {
        // prefetch input gates early (latency overlaps the dot-product loop)
        float ir0 = 0.f, iz0 = 0.f, in0 = 0.f;
        if (half == 0) {
            const float* gi = &g_gi[(t*BB + b)*768];
            ir0 = gi[j0+jl]; iz0 = gi[256 + j0+jl]; in0 = gi[512 + j0+jl];
        }
        const float* hin = g_hbuf[t & 1];
        for (int i = tid; i < BB*HID; i += 256) h_s[i] = __ldcg(&hin[i]);
        __syncthreads();
        float ar = 0.f, az = 0.f, an = 0.f;
        const float4* h4  = (const float4*)&h_s[b*256 + half*128];
        const float4* wr4 = (const float4*)&ws[(0*8 + jl)*256 + half*128];
        const float4* wz4 = (const float4*)&ws[(1*8 + jl)*256 + half*128];
        const float4* wn4 = (const float4*)&ws[(2*8 + jl)*256 + half*128];
#pragma unroll 8
        for (int k = 0; k < 32; k++) {
            float4 hv = h4[k];
            float4 a = wr4[k]; ar += a.x*hv.x + a.y*hv.y + a.z*hv.z + a.w*hv.w;
            float4 c = wz4[k]; az += c.x*hv.x + c.y*hv.y + c.z*hv.z + c.w*hv.w;
            float4 d = wn4[k]; an += d.x*hv.x + d.y*hv.y + d.z*hv.z + d.w*hv.w;
        }
        int pb = ((b*8 + jl)*2 + half)*3;
        part[pb+0] = ar; part[pb+1] = az; part[pb+2] = an;
        __syncthreads();
        if (half == 0) {
            int p2 = ((b*8 + jl)*2)*3;
            float hr = part[p2+0] + part[p2+3] + bhh_s[jl];
            float hz = part[p2+1] + part[p2+4] + bhh_s[8+jl];
            float hn = part[p2+2] + part[p2+5] + bhh_s[16+jl];
            float ir  = ir0 + bih_s[jl];
            float iz  = iz0 + bih_s[8+jl];
            float in_ = in0 + bih_s[16+jl];
            float r  = 1.f / (1.f + expf(-(ir + hr)));
            float zg = 1.f / (1.f + expf(-(iz + hz)));
            float n  = tanhf(in_ + r*hn);
            float hprev = h_s[b*256 + j0 + jl];
            float hnew = (1.f - zg)*n + zg*hprev;
            __stcg(&g_hbuf[(t+1) & 1][b*256 + j0 + jl], hnew);
            if (t == ts_s[b]) g_ct[b*256 + j0 + jl] = hnew;
        }
        __syncthreads();
        if (tid == 0) {
            __threadfence();
            unsigned old = atomicAdd(barcnt, 1u);
            unsigned target = 32u * (unsigned)(t + 1);
            if (old == target - 1u) {
                __threadfence();
                *(volatile unsigned*)epoch = target;   // publish on its own line
            }
            while (*(volatile unsigned*)epoch < target) { }   // read-only spin, no RMW on this line
            __threadfence();
        }
        __syncthreads();
    }
}

__global__ void enc_kernel(const int* __restrict__ ts, const float* __restrict__ sc,
                           const float* __restrict__ sh) {
    int k = blockIdx.x, b = blockIdx.y, d = threadIdx.x;
    int t = ts[b] + k + 1;
    float r = g_c5[(b*CC + d)*L5 + t];
    g_enc[(k*BB + b)*CC + d] = fmaxf(fmaf(r, sc[d], sh[d]), 0.f);
}

__global__ void pred_kernel(const float* __restrict__ wk, const float* __restrict__ wkb) {
    int k = blockIdx.x, b = blockIdx.y, d = threadIdx.x;
    __shared__ float ct[HID];
    if (d < HID) ct[d] = g_ct[b*HID + d];
    __syncthreads();
    float acc = wkb[k*CC + d];
    const float4* w4 = (const float4*)&wk[(k*CC + d)*HID];
#pragma unroll 4
    for (int h = 0; h < HID/4; h++) {
        float4 w = w4[h];
        const float* c = &ct[h*4];
        acc += w.x*c[0] + w.y*c[1] + w.z*c[2] + w.w*c[3];
    }
    g_pred[(k*BB + b)*CC + d] = acc;
}

__global__ void total_kernel() {
    int k = blockIdx.x, tid = threadIdx.x;
    int b = tid >> 4, c = tid & 15;
    const float* e = &g_enc[(k*BB + b)*CC];
    const float* p = &g_pred[(k*BB + c)*CC];
    float acc = 0.f;
    for (int d = 0; d < CC; d++) acc += e[d] * p[d];
    g_total[(k*BB + b)*BB + c] = acc;
}

__global__ void final_kernel(float* __restrict__ out) {
    __shared__ float lse_s[KCPC*BB];
    __shared__ float contrib[KCPC*BB];
    __shared__ int corr[BB];
    int tid = threadIdx.x;
    if (tid < KCPC*BB) {
        int b = tid & 15;
        const float* row = &g_total[tid*BB];
        float m = row[0];
        for (int c = 1; c < BB; c++) m = fmaxf(m, row[c]);
        float s = 0.f;
        for (int c = 0; c < BB; c++) s += expf(row[c] - m);
        float lse = m + logf(s);
        lse_s[tid] = lse;
        contrib[tid] = row[b] - lse;
    }
    __syncthreads();
    if (tid == 0) {
        float s = 0.f;
        for (int i = 0; i < KCPC*BB; i++) s += contrib[i];
        out[1] = s / (-(float)(BB*KCPC));
    }
    if (tid < BB) {
        int c = tid;
        float best = -1e30f; int bi = -1;
        for (int b = 0; b < BB; b++) {
            float v = g_total[((KCPC-1)*BB + b)*BB + c] - lse_s[(KCPC-1)*BB + b];
            if (v > best) { best = v; bi = b; }
        }
        corr[tid] = (bi == c) ? 1 : 0;
    }
    __syncthreads();
    if (tid == 0) {
        int cs = 0;
        for (int i = 0; i < BB; i++) cs += corr[i];
        out[0] = (float)cs / (float)BB;
    }
    for (int i = tid; i < BB*HID; i += blockDim.x) out[2 + i] = g_hbuf[0][i];
}

extern "C" void kernel_launch(void* const* d_in, const int* in_sizes, int n_in,
                              void* d_out, int out_size) {
    (void)in_sizes; (void)n_in; (void)out_size;
    const float* x      = (const float*)d_in[0];
    const float* hidden = (const float*)d_in[1];
    const int*   tsamp  = (const int*)d_in[3];
    const float* w1     = (const float*)d_in[4];
    const float* w2     = (const float*)d_in[5];
    const float* w345   = (const float*)d_in[6];
    const float* gamma  = (const float*)d_in[7];
    const float* beta   = (const float*)d_in[8];
    const float* wih    = (const float*)d_in[9];
    const float* whh    = (const float*)d_in[10];
    const float* bih    = (const float*)d_in[11];
    const float* bhh    = (const float*)d_in[12];
    const float* wk     = (const float*)d_in[13];
    const float* wkb    = (const float*)d_in[14];
    float* out = (float*)d_out;

    float *p_c1, *p_c2, *p_c3, *p_c4, *p_c5, *p_sc, *p_sh;
    uint32_t *p_w2b, *p_w345b, *p_apb;
    unsigned *p_bar, *p_ep, *p_dbar, *p_dep;
    cudaGetSymbolAddress((void**)&p_c1, g_c1);
    cudaGetSymbolAddress((void**)&p_c2, g_c2);
    cudaGetSymbolAddress((void**)&p_c3, g_c3);
    cudaGetSymbolAddress((void**)&p_c4, g_c4);
    cudaGetSymbolAddress((void**)&p_c5, g_c5);
    cudaGetSymbolAddress((void**)&p_sc, g_scale);
    cudaGetSymbolAddress((void**)&p_sh, g_shift);
    cudaGetSymbolAddress((void**)&p_w2b, g_w2b);
    cudaGetSymbolAddress((void**)&p_w345b, g_w345b);
    cudaGetSymbolAddress((void**)&p_apb, g_apb);
    cudaGetSymbolAddress((void**)&p_bar, g_bar_cnt);
    cudaGetSymbolAddress((void**)&p_ep, g_epoch);
    cudaGetSymbolAddress((void**)&p_dbar, g_dbar);
    cudaGetSymbolAddress((void**)&p_dep, g_depoch);

    const int SM_L2   = (32 + 3*(5120 + 8*260))*4;
    const int SM_L345 = (32 + 3*(5120 + 16*144))*4;
    cudaFuncSetAttribute(conv_tc_kernel<8,4,4096,8200,260>,
                         cudaFuncAttributeMaxDynamicSharedMemorySize, SM_L2);
    cudaFuncSetAttribute(conv_tc_kernel<4,2,2048,2064,144>,
                         cudaFuncAttributeMaxDynamicSharedMemorySize, SM_L345);
    cudaFuncSetAttribute(conv_tc_kernel<4,2,2048,1040,144>,
                         cudaFuncAttributeMaxDynamicSharedMemorySize, SM_L345);
    cudaFuncSetAttribute(conv_tc_kernel<4,2,2048,528,144>,
                         cudaFuncAttributeMaxDynamicSharedMemorySize, SM_L345);

    conv1_kernel<<<dim3(63, BB), 256>>>(x, w1);                               // 1
    statsprep_kernel<L1,8200,2><<<CC, 256>>>(p_c1, gamma, beta, p_sc, p_sh);  // 2
    reset_dummy_kernel<<<1, 1>>>();                                           // 3
    gru_kernel<64><<<32, 256>>>(whh, bih, bhh, tsamp, p_dbar, p_dep);         // 4 (profiled: GRU internals)
    prepw_kernel<4096><<<(512*2048 + 255)/256, 256>>>(w2, p_w2b);             // 5
    conv_tc_kernel<8,4,4096,8200,260><<<dim3(32, 4, BB), 256, SM_L2>>>(       // 6
        p_apb, p_w2b, p_c2, L2);

    init_kernel<<<16, 256>>>(hidden);
    prepw_kernel<2048><<<(512*1024 + 255)/256, 256>>>(w345 + 0*512*2048, p_w345b + 0*655360);
    prepw_kernel<2048><<<(512*1024 + 255)/256, 256>>>(w345 + 1*512*2048, p_w345b + 1*655360);
    prepw_kernel<2048><<<(512*1024 + 255)/256, 256>>>(w345 + 2*512*2048, p_w345b + 2*655360);

    statsprep_kernel<L2,2064,1><<<CC, 256>>>(p_c2, gamma + CC, beta + CC, p_sc + CC, p_sh + CC);
    conv_tc_kernel<4,2,2048,2064,144><<<dim3(16, 4, BB), 256, SM_L345>>>(
        p_apb, p_w345b + 0*655360, p_c3, L3);

    statsprep_kernel<L3,1040,1><<<CC, 256>>>(p_c3, gamma + 2*CC, beta + 2*CC, p_sc + 2*CC, p_sh + 2*CC);
    conv_tc_kernel<4,2,2048,1040,144><<<dim3(8, 4, BB), 256, SM_L345>>>(
        p_apb, p_w345b + 1*655360, p_c4, L4);

    statsprep_kernel<L4,528,1><<<CC, 256>>>(p_c4, gamma + 3*CC, beta + 3*CC, p_sc + 3*CC, p_sh + 3*CC);
    conv_tc_kernel<4,2,2048,528,144><<<dim3(4, 4, BB), 256, SM_L345>>>(
        p_apb, p_w345b + 2*655360, p_c5, L5);

    stats_kernel<<<CC, 256>>>(p_c5, gamma + 4*CC, beta + 4*CC, p_sc + 4*CC, p_sh + 4*CC, L5);

    buildz_kernel<<<dim3(TT, BB), CC>>>(tsamp, p_sc + 4*CC, p_sh + 4*CC);
    gi_gemm_kernel<<<dim3(125, 12), 256>>>(wih);
    gru_kernel<TT><<<32, 256>>>(whh, bih, bhh, tsamp, p_bar, p_ep);

    enc_kernel<<<dim3(KCPC, BB), CC>>>(tsamp, p_sc + 4*CC, p_sh + 4*CC);
    pred_kernel<<<dim3(KCPC, BB), CC>>>(wk, wkb);
    total_kernel<<<KCPC, 256>>>();
    final_kernel<<<1, 256>>>(out);
}

// round 17
// speedup vs baseline: 1.8248x; 1.8248x over previous
#include <cuda_runtime.h>
#include <cuda_fp16.h>
#include <math.h>
#include <stdint.h>

#define BB 16
#define CC 512
#define L0 80000
#define L1 16000
#define L2 4000
#define L3 2000
#define L4 1000
#define L5 500
#define TT 500
#define HID 256
#define KCPC 12

__device__ float g_c1[BB*CC*L1];
__device__ float g_c2[BB*CC*L2];
__device__ float g_c3[BB*CC*L3];
__device__ float g_c4[BB*CC*L4];
__device__ float g_c5[BB*CC*L5];
__device__ float g_scale[5*CC];
__device__ float g_shift[5*CC];
__device__ uint32_t g_w2b[1310720];
__device__ uint32_t g_w345b[3*655360];
__device__ uint32_t g_apb[(size_t)BB*CC*8200];
__device__ float g_z[TT*BB*CC];
__device__ float g_gi[TT*BB*768];
__device__ float g_hbuf[2][BB*HID];
__device__ float g_ct[BB*HID];
__device__ float g_enc[KCPC*BB*CC];
__device__ float g_pred[KCPC*BB*CC];
__device__ float g_total[KCPC*BB*BB];

__device__ __forceinline__ uint32_t smem_to_u32(const void* p) {
    uint32_t a;
    asm("{ .reg .u64 t; cvta.to.shared.u64 t, %1; cvt.u32.u64 %0, t; }" : "=r"(a) : "l"(p));
    return a;
}
__device__ __forceinline__ uint32_t pack_h2(float v0, float v1) {
    __half2 h = __floats2half2_rn(v0, v1);
    return *(uint32_t*)&h;
}
__device__ __forceinline__ void mma_fp16(float* d, const uint32_t* a, const uint32_t* bfr) {
    asm volatile(
        "mma.sync.aligned.m16n8k16.row.col.f32.f16.f16.f32 "
        "{%0,%1,%2,%3}, {%4,%5,%6,%7}, {%8,%9}, {%0,%1,%2,%3};"
        : "+f"(d[0]), "+f"(d[1]), "+f"(d[2]), "+f"(d[3])
        : "r"(a[0]), "r"(a[1]), "r"(a[2]), "r"(a[3]), "r"(bfr[0]), "r"(bfr[1]));
}
#define MBARRIER_INIT(addr, cnt) \
    asm volatile("mbarrier.init.shared.b64 [%0], %1;" :: "r"((uint32_t)(addr)), "r"((uint32_t)(cnt)) : "memory")
#define MBARRIER_EXPECT_TX(addr, bytes) \
    asm volatile("mbarrier.arrive.expect_tx.shared.b64 _, [%0], %1;" :: "r"((uint32_t)(addr)), "r"((uint32_t)(bytes)) : "memory")
#define MBARRIER_WAIT_PARITY(addr, par) do { \
    uint32_t _m = (uint32_t)(addr); uint32_t _p = (uint32_t)(par); uint32_t _d; \
    asm volatile("{\n\t.reg .pred p;\n\tmbarrier.try_wait.parity.shared.b64 p, [%1], %2;\n\tselp.b32 %0, 1, 0, p;\n\t}" \
        : "=r"(_d) : "r"(_m), "r"(_p) : "memory"); \
    if (!_d) { \
        asm volatile("{\n\t.reg .pred P1;\n\tWL_%=:\n\tmbarrier.try_wait.parity.shared.b64 P1, [%0], %1;\n\t@P1 bra.uni WD_%=;\n\tbra.uni WL_%=;\n\tWD_%=:\n\t}" \
            :: "r"(_m), "r"(_p) : "memory"); \
    } \
} while (0)
#define BULK_G2S(dst, src, bytes, mb) \
    asm volatile("cp.async.bulk.shared::cluster.global.mbarrier::complete_tx::bytes [%0], [%1], %2, [%3];" \
        :: "r"((uint32_t)(dst)), "l"(src), "r"((uint32_t)(bytes)), "r"((uint32_t)(mb)) : "memory")
#define CLUSTER_SYNC() do { \
    asm volatile("barrier.cluster.arrive.aligned;" ::: "memory"); \
    asm volatile("barrier.cluster.wait.aligned;" ::: "memory"); \
} while (0)
#define STS_CLUSTER_F32(laddr, rank, val) \
    asm volatile("{ .reg .b32 ra; mapa.shared::cluster.u32 ra, %0, %1; st.shared::cluster.f32 [ra], %2; }" \
        :: "r"((uint32_t)(laddr)), "r"((uint32_t)(rank)), "f"(val) : "memory")

__global__ void init_kernel(const float* __restrict__ hidden) {
    int i = blockIdx.x * blockDim.x + threadIdx.x;
    if (i < BB*HID) g_hbuf[0][i] = hidden[i];
}

template<int KTOT>
__global__ void prepw_kernel(const float* __restrict__ w, uint32_t* __restrict__ wb) {
    int i = blockIdx.x*256 + threadIdx.x;
    if (i >= 512*(KTOT/2)) return;
    int co = i / (KTOT/2), wp = i % (KTOT/2);
    int chunk = wp >> 5, word = wp & 31;
    size_t d = (((size_t)chunk*4 + (co>>7))*128 + (co&127))*40 + word;
    wb[d] = pack_h2(w[(size_t)co*KTOT + 2*wp], w[(size_t)co*KTOT + 2*wp + 1]);
}

template<int LIN, int LPW, int SH>
__global__ void statsprep_kernel(const float* __restrict__ raw, const float* __restrict__ gamma,
                                 const float* __restrict__ beta, float* __restrict__ scale,
                                 float* __restrict__ shift) {
    int c = blockIdx.x, tid = threadIdx.x;
    double s = 0.0, s2 = 0.0;
    for (int b = 0; b < BB; b++) {
        const float* p = raw + (size_t)(b*CC + c)*LIN;
        for (int l = tid; l < LIN; l += 256) { float v = p[l]; s += v; s2 += (double)v*v; }
    }
    __shared__ double rs[256], rs2[256];
    __shared__ float sc_s, sh_s;
    rs[tid] = s; rs2[tid] = s2; __syncthreads();
    for (int st = 128; st > 0; st >>= 1) {
        if (tid < st) { rs[tid] += rs[tid+st]; rs2[tid] += rs2[tid+st]; }
        __syncthreads();
    }
    if (tid == 0) {
        double n = (double)BB * (double)LIN;
        double mean = rs[0]/n, var = rs2[0]/n - mean*mean;
        double scd = (double)gamma[c] / sqrt(var + 1e-5);
        float scf = (float)scd;
        float shf = (float)((double)beta[c] - mean*scd);
        scale[c] = scf; shift[c] = shf;
        sc_s = scf; sh_s = shf;
    }
    __syncthreads();
    float scf = sc_s, shf = sh_s;
    for (int b = 0; b < BB; b++) {
        const float* src = raw + (size_t)(b*CC + c)*LIN;
        uint32_t* db = g_apb + ((size_t)(b*CC) + c)*LPW;
        for (int w = tid; w < LPW; w += 256) {
            int p0 = 2*w - SH;
            float v0 = (p0 >= 0 && p0 < LIN) ? fmaxf(fmaf(src[p0], scf, shf), 0.f) : 0.f;
            float v1 = (p0+1 >= 0 && p0+1 < LIN) ? fmaxf(fmaf(src[p0+1], scf, shf), 0.f) : 0.f;
            db[w] = pack_h2(v0, v1);
        }
    }
}

__global__ void conv1_kernel(const float* __restrict__ x, const float* __restrict__ w) {
    __shared__ float wsm[CC*10];
    __shared__ float xs[256*5 + 10];
    int b = blockIdx.y, o0 = blockIdx.x * 256, tid = threadIdx.x;
    for (int i = tid; i < CC*10; i += 256) wsm[i] = w[i];
    int p0 = o0*5 - 3;
    for (int i = tid; i < 256*5 + 10; i += 256) {
        int p = p0 + i;
        xs[i] = (p >= 0 && p < L0) ? x[b*L0 + p] : 0.f;
    }
    __syncthreads();
    int o = o0 + tid;
    if (o >= L1) return;
    float xr[10];
#pragma unroll
    for (int j = 0; j < 10; j++) xr[j] = xs[tid*5 + j];
    for (int co = 0; co < CC; co++) {
        float acc = 0.f;
#pragma unroll
        for (int j = 0; j < 10; j++) acc = fmaf(wsm[co*10 + j], xr[j], acc);
        g_c1[(b*CC + co)*L1 + o] = acc;
    }
}

__global__ void stats_kernel(const float* __restrict__ raw, const float* __restrict__ gamma,
                             const float* __restrict__ beta, float* __restrict__ scale,
                             float* __restrict__ shift, int L) {
    int c = blockIdx.x, tid = threadIdx.x;
    double s = 0.0, s2 = 0.0;
    for (int b = 0; b < BB; b++) {
        const float* p = raw + (size_t)(b*CC + c)*L;
        for (int l = tid; l < L; l += 256) { float v = p[l]; s += v; s2 += (double)v*v; }
    }
    __shared__ double rs[256], rs2[256];
    rs[tid] = s; rs2[tid] = s2; __syncthreads();
    for (int st = 128; st > 0; st >>= 1) {
        if (tid < st) { rs[tid] += rs[tid+st]; rs2[tid] += rs2[tid+st]; }
        __syncthreads();
    }
    if (tid == 0) {
        double n = (double)BB * (double)L;
        double mean = rs[0]/n, var = rs2[0]/n - mean*mean;
        double sc = (double)gamma[c] / sqrt(var + 1e-5);
        scale[c] = (float)sc;
        shift[c] = (float)((double)beta[c] - mean*sc);
    }
}

template<int KW, int S, int KTOT, int LPW, int NW>
__global__ void __launch_bounds__(256, 2)
conv_tc_kernel(const uint32_t* __restrict__ pb, const uint32_t* __restrict__ wb,
               float* __restrict__ out, int Lout) {
    constexpr int CI = 64/KW, NC = KTOT/64;
    constexpr int AW = 5120;
    constexpr int BSTW = CI*NW;
    constexpr int STGW = AW + BSTW;
    constexpr int HDR = 32;
    extern __shared__ __align__(128) uint32_t smw[];
    uint32_t sbase = smem_to_u32(smw);
    int tid = threadIdx.x, wid = tid >> 5, lane = tid & 31;
    int g = lane >> 2, tig = lane & 3;
    int warp_m = wid >> 1, warp_n = wid & 1;
    int n0 = blockIdx.x*128, b = blockIdx.z;
    uint32_t txb = (uint32_t)(20480 + CI*NW*4);

    if (tid == 0) { MBARRIER_INIT(sbase, 1); MBARRIER_INIT(sbase + 8, 1); MBARRIER_INIT(sbase + 16, 1); }
    __syncthreads();
    asm volatile("fence.proxy.async;" ::: "memory");

    auto issue = [&](int c, int s) {
        uint32_t mb = sbase + s*8;
        uint32_t ast = sbase + (uint32_t)(HDR + s*STGW)*4;
        uint32_t bst = ast + AW*4;
        MBARRIER_EXPECT_TX(mb, txb);
        size_t aoff = ((size_t)c*4 + blockIdx.y)*AW;
        BULK_G2S(ast, wb + aoff, 20480, mb);
        int base = n0*(S/2);
        for (int r = 0; r < CI; r++) {
            size_t so = ((size_t)(b*CC) + (size_t)c*CI + r)*LPW + base;
            BULK_G2S(bst + (uint32_t)(r*NW)*4, pb + so, NW*4, mb);
        }
    };
    if (tid == 0) { issue(0, 0); issue(1, 1); if (NC > 2) issue(2, 2); }

    float acc[2][8][4];
#pragma unroll
    for (int mt = 0; mt < 2; mt++)
#pragma unroll
        for (int nt = 0; nt < 8; nt++)
#pragma unroll
            for (int q = 0; q < 4; q++) acc[mt][nt][q] = 0.f;

    int ph[3] = {0, 0, 0};
    int s = 0;
    for (int c = 0; c < NC; c++) {
        MBARRIER_WAIT_PARITY(sbase + s*8, ph[s]); ph[s] ^= 1;
        int Ab = HDR + s*STGW;
        int Bb = Ab + AW;
#pragma unroll
        for (int ks = 0; ks < 4; ks++) {
            int kw = ks*8;
            uint32_t ab[2][4];
#pragma unroll
            for (int mt = 0; mt < 2; mt++) {
                int r = warp_m*32 + mt*16 + g;
                ab[mt][0] = smw[Ab + r*40 + kw + tig];
                ab[mt][1] = smw[Ab + (r+8)*40 + kw + tig];
                ab[mt][2] = smw[Ab + r*40 + kw + tig + 4];
                ab[mt][3] = smw[Ab + (r+8)*40 + kw + tig + 4];
            }
#pragma unroll
            for (int nt = 0; nt < 8; nt++) {
                int nl = warp_n*64 + nt*8 + g;
                uint32_t bbf[2];
#pragma unroll
                for (int j = 0; j < 2; j++) {
                    int kk = ks*16 + 8*j + 2*tig;
                    int cil = kk / KW, jj = kk - cil*KW;
                    bbf[j] = smw[Bb + cil*NW + nl*(S/2) + (jj >> 1)];
                }
#pragma unroll
                for (int mt = 0; mt < 2; mt++)
                    mma_fp16(acc[mt][nt], ab[mt], bbf);
            }
        }
        __syncthreads();
        if (tid == 0 && c + 3 < NC) issue(c + 3, s);
        s = (s == 2) ? 0 : s + 1;
    }

#pragma unroll
    for (int mt = 0; mt < 2; mt++) {
        int co0 = blockIdx.y*128 + warp_m*32 + mt*16 + g;
#pragma unroll
        for (int nt = 0; nt < 8; nt++) {
            int n = n0 + warp_n*64 + nt*8 + 2*tig;
            if (n < Lout) {
                *(float2*)&out[(size_t)(b*CC + co0)*Lout + n]     = make_float2(acc[mt][nt][0], acc[mt][nt][1]);
                *(float2*)&out[(size_t)(b*CC + co0 + 8)*Lout + n] = make_float2(acc[mt][nt][2], acc[mt][nt][3]);
            }
        }
    }
}

__global__ void buildz_kernel(const int* __restrict__ ts, const float* __restrict__ sc,
                              const float* __restrict__ sh) {
    int t = blockIdx.x, b = blockIdx.y, d = threadIdx.x;
    float v = 0.f;
    if (t <= ts[b]) {
        float r = g_c5[(b*CC + d)*L5 + t];
        v = fmaxf(fmaf(r, sc[d], sh[d]), 0.f);
    }
    g_z[(t*BB + b)*CC + d] = v;
}

__global__ void gi_gemm_kernel(const float* __restrict__ wih) {
    __shared__ float As[16*65];
    __shared__ float Bs[16*65];
    int tid = threadIdx.x, tx = tid & 15, ty = tid >> 4;
    int r0 = blockIdx.x * 64, g0 = blockIdx.y * 64;
    float acc[4][4] = {};
    for (int k0 = 0; k0 < CC; k0 += 16) {
        for (int i = tid; i < 1024; i += 256) {
            int rl = i >> 4, kk = i & 15;
            As[kk*65 + rl] = g_z[(r0+rl)*CC + k0 + kk];
            Bs[kk*65 + rl] = wih[(g0+rl)*CC + k0 + kk];
        }
        __syncthreads();
#pragma unroll
        for (int kk = 0; kk < 16; kk++) {
            float av[4], bv[4];
#pragma unroll
            for (int i = 0; i < 4; i++) av[i] = As[kk*65 + ty*4 + i];
#pragma unroll
            for (int j = 0; j < 4; j++) bv[j] = Bs[kk*65 + tx*4 + j];
#pragma unroll
            for (int i = 0; i < 4; i++)
#pragma unroll
                for (int j = 0; j < 4; j++)
                    acc[i][j] = fmaf(av[i], bv[j], acc[i][j]);
        }
        __syncthreads();
    }
#pragma unroll
    for (int i = 0; i < 4; i++)
#pragma unroll
        for (int j = 0; j < 4; j++)
            g_gi[(r0 + ty*4 + i)*768 + g0 + tx*4 + j] = acc[i][j];
}

// ===== clustered GRU: 1 cluster of 8 CTAs, hardware cluster.sync, DSMEM exchange =====
// CTA c: owns gate rows [c*96, c*96+96) and h-units [c*32, c*32+32).
__global__ void __cluster_dims__(8, 1, 1) __launch_bounds__(256, 1)
gruclu_kernel(const float* __restrict__ whh, const float* __restrict__ bih,
              const float* __restrict__ bhh, const int* __restrict__ ts) {
    extern __shared__ __align__(16) float sm[];
    float* ws    = sm;                 // [96][256]
    float* h_s   = ws + 96*256;        // [16][260]
    float* grecv = h_s + 16*260;       // [16][100] : g*32+jl
    __shared__ float bihs[96], bhhs[96];
    __shared__ int tss[BB];
    int tid = threadIdx.x;
    int c = blockIdx.x;

    for (int i = tid; i < 96*64; i += 256)
        ((float4*)ws)[i] = ((const float4*)(whh + (size_t)c*96*256))[i];
    for (int i = tid; i < BB*HID; i += 256)
        h_s[(i >> 8)*260 + (i & 255)] = g_hbuf[0][i];
    if (tid < 96) {
        int g = tid/32, jl = tid%32;
        bihs[tid] = bih[g*256 + c*32 + jl];
        bhhs[tid] = bhh[g*256 + c*32 + jl];
    }
    if (tid < BB) tss[tid] = ts[tid];
    __syncthreads();
    CLUSTER_SYNC();

    int b = tid & 15, u2 = tid >> 4;
    const float* wbase = ws + u2*6*256;
    const float* hrow = h_s + b*260;
    uint32_t grecv_u32 = smem_to_u32(grecv);
    uint32_t hs_u32 = smem_to_u32(h_s);

    // precompute deposit targets for my 6 rows
    uint32_t dep_addr[6]; uint32_t dep_rank[6];
#pragma unroll
    for (int i = 0; i < 6; i++) {
        int grow = c*96 + u2*6 + i;
        int g = grow >> 8, j = grow & 255;
        dep_rank[i] = (uint32_t)(j >> 5);
        dep_addr[i] = grecv_u32 + (uint32_t)((b*100 + g*32 + (j & 31))*4);
    }
    int upd_b[2], upd_j[2];
#pragma unroll
    for (int p = 0; p < 2; p++) {
        int idx = tid*2 + p;
        upd_b[p] = idx >> 5;
        upd_j[p] = c*32 + (idx & 31);
    }

    for (int t = 0; t < TT; t++) {
        // prefetch gi for update phase
        float pir[2], piz[2], pin[2];
#pragma unroll
        for (int p = 0; p < 2; p++) {
            const float* gi = &g_gi[(t*BB + upd_b[p])*768];
            pir[p] = __ldg(&gi[upd_j[p]]);
            piz[p] = __ldg(&gi[256 + upd_j[p]]);
            pin[p] = __ldg(&gi[512 + upd_j[p]]);
        }
        float acc[6] = {0.f, 0.f, 0.f, 0.f, 0.f, 0.f};
#pragma unroll 4
        for (int k4 = 0; k4 < 64; k4++) {
            float4 h4 = ((const float4*)hrow)[k4];
#pragma unroll
            for (int i = 0; i < 6; i++) {
                float4 w4 = ((const float4*)(wbase + i*256))[k4];
                acc[i] = fmaf(w4.x, h4.x, acc[i]);
                acc[i] = fmaf(w4.y, h4.y, acc[i]);
                acc[i] = fmaf(w4.z, h4.z, acc[i]);
                acc[i] = fmaf(w4.w, h4.w, acc[i]);
            }
        }
#pragma unroll
        for (int i = 0; i < 6; i++)
            STS_CLUSTER_F32(dep_addr[i], dep_rank[i], acc[i]);
        CLUSTER_SYNC();

#pragma unroll
        for (int p = 0; p < 2; p++) {
            int ub = upd_b[p], j = upd_j[p], jl = j & 31;
            float hr = grecv[ub*100 + jl]      + bhhs[jl];
            float hz = grecv[ub*100 + 32 + jl] + bhhs[32+jl];
            float hn = grecv[ub*100 + 64 + jl] + bhhs[64+jl];
            float ir  = pir[p] + bihs[jl];
            float iz  = piz[p] + bihs[32+jl];
            float in_ = pin[p] + bihs[64+jl];
            float r  = 1.f / (1.f + expf(-(ir + hr)));
            float zg = 1.f / (1.f + expf(-(iz + hz)));
            float n  = tanhf(in_ + r*hn);
            float hprev = h_s[ub*260 + j];
            float hnew = (1.f - zg)*n + zg*hprev;
            if (t == tss[ub]) g_ct[ub*256 + j] = hnew;
            uint32_t ha = hs_u32 + (uint32_t)((ub*260 + j)*4);
#pragma unroll
            for (int rk = 0; rk < 8; rk++)
                STS_CLUSTER_F32(ha, (uint32_t)rk, hnew);
        }
        CLUSTER_SYNC();
    }
    // write final hidden for output
#pragma unroll
    for (int p = 0; p < 2; p++)
        g_hbuf[0][upd_b[p]*256 + upd_j[p]] = h_s[upd_b[p]*260 + upd_j[p]];
    CLUSTER_SYNC();
}

__global__ void enc_kernel(const int* __restrict__ ts, const float* __restrict__ sc,
                           const float* __restrict__ sh) {
    int k = blockIdx.x, b = blockIdx.y, d = threadIdx.x;
    int t = ts[b] + k + 1;
    float r = g_c5[(b*CC + d)*L5 + t];
    g_enc[(k*BB + b)*CC + d] = fmaxf(fmaf(r, sc[d], sh[d]), 0.f);
}

__global__ void pred_kernel(const float* __restrict__ wk, const float* __restrict__ wkb) {
    int k = blockIdx.x, b = blockIdx.y, d = threadIdx.x;
    __shared__ float ct[HID];
    if (d < HID) ct[d] = g_ct[b*HID + d];
    __syncthreads();
    float acc = wkb[k*CC + d];
    const float4* w4 = (const float4*)&wk[(k*CC + d)*HID];
#pragma unroll 4
    for (int h = 0; h < HID/4; h++) {
        float4 w = w4[h];
        const float* c = &ct[h*4];
        acc += w.x*c[0] + w.y*c[1] + w.z*c[2] + w.w*c[3];
    }
    g_pred[(k*BB + b)*CC + d] = acc;
}

__global__ void total_kernel() {
    int k = blockIdx.x, tid = threadIdx.x;
    int b = tid >> 4, c = tid & 15;
    const float* e = &g_enc[(k*BB + b)*CC];
    const float* p = &g_pred[(k*BB + c)*CC];
    float acc = 0.f;
    for (int d = 0; d < CC; d++) acc += e[d] * p[d];
    g_total[(k*BB + b)*BB + c] = acc;
}

__global__ void final_kernel(float* __restrict__ out) {
    __shared__ float lse_s[KCPC*BB];
    __shared__ float contrib[KCPC*BB];
    __shared__ int corr[BB];
    int tid = threadIdx.x;
    if (tid < KCPC*BB) {
        int b = tid & 15;
        const float* row = &g_total[tid*BB];
        float m = row[0];
        for (int c = 1; c < BB; c++) m = fmaxf(m, row[c]);
        float s = 0.f;
        for (int c = 0; c < BB; c++) s += expf(row[c] - m);
        float lse = m + logf(s);
        lse_s[tid] = lse;
        contrib[tid] = row[b] - lse;
    }
    __syncthreads();
    if (tid == 0) {
        float s = 0.f;
        for (int i = 0; i < KCPC*BB; i++) s += contrib[i];
        out[1] = s / (-(float)(BB*KCPC));
    }
    if (tid < BB) {
        int c = tid;
        float best = -1e30f; int bi = -1;
        for (int b = 0; b < BB; b++) {
            float v = g_total[((KCPC-1)*BB + b)*BB + c] - lse_s[(KCPC-1)*BB + b];
            if (v > best) { best = v; bi = b; }
        }
        corr[tid] = (bi == c) ? 1 : 0;
    }
    __syncthreads();
    if (tid == 0) {
        int cs = 0;
        for (int i = 0; i < BB; i++) cs += corr[i];
        out[0] = (float)cs / (float)BB;
    }
    for (int i = tid; i < BB*HID; i += blockDim.x) out[2 + i] = g_hbuf[0][i];
}

extern "C" void kernel_launch(void* const* d_in, const int* in_sizes, int n_in,
                              void* d_out, int out_size) {
    (void)in_sizes; (void)n_in; (void)out_size;
    const float* x      = (const float*)d_in[0];
    const float* hidden = (const float*)d_in[1];
    const int*   tsamp  = (const int*)d_in[3];
    const float* w1     = (const float*)d_in[4];
    const float* w2     = (const float*)d_in[5];
    const float* w345   = (const float*)d_in[6];
    const float* gamma  = (const float*)d_in[7];
    const float* beta   = (const float*)d_in[8];
    const float* wih    = (const float*)d_in[9];
    const float* whh    = (const float*)d_in[10];
    const float* bih    = (const float*)d_in[11];
    const float* bhh    = (const float*)d_in[12];
    const float* wk     = (const float*)d_in[13];
    const float* wkb    = (const float*)d_in[14];
    float* out = (float*)d_out;

    float *p_c1, *p_c2, *p_c3, *p_c4, *p_c5, *p_sc, *p_sh;
    uint32_t *p_w2b, *p_w345b, *p_apb;
    cudaGetSymbolAddress((void**)&p_c1, g_c1);
    cudaGetSymbolAddress((void**)&p_c2, g_c2);
    cudaGetSymbolAddress((void**)&p_c3, g_c3);
    cudaGetSymbolAddress((void**)&p_c4, g_c4);
    cudaGetSymbolAddress((void**)&p_c5, g_c5);
    cudaGetSymbolAddress((void**)&p_sc, g_scale);
    cudaGetSymbolAddress((void**)&p_sh, g_shift);
    cudaGetSymbolAddress((void**)&p_w2b, g_w2b);
    cudaGetSymbolAddress((void**)&p_w345b, g_w345b);
    cudaGetSymbolAddress((void**)&p_apb, g_apb);

    const int SM_L2   = (32 + 3*(5120 + 8*260))*4;
    const int SM_L345 = (32 + 3*(5120 + 16*144))*4;
    const int SM_GRU  = (96*256 + 16*260 + 16*100)*4;   // 121344
    cudaFuncSetAttribute(conv_tc_kernel<8,4,4096,8200,260>,
                         cudaFuncAttributeMaxDynamicSharedMemorySize, SM_L2);
    cudaFuncSetAttribute(conv_tc_kernel<4,2,2048,2064,144>,
                         cudaFuncAttributeMaxDynamicSharedMemorySize, SM_L345);
    cudaFuncSetAttribute(conv_tc_kernel<4,2,2048,1040,144>,
                         cudaFuncAttributeMaxDynamicSharedMemorySize, SM_L345);
    cudaFuncSetAttribute(conv_tc_kernel<4,2,2048,528,144>,
                         cudaFuncAttributeMaxDynamicSharedMemorySize, SM_L345);
    cudaFuncSetAttribute(gruclu_kernel,
                         cudaFuncAttributeMaxDynamicSharedMemorySize, SM_GRU);

    conv1_kernel<<<dim3(63, BB), 256>>>(x, w1);
    statsprep_kernel<L1,8200,2><<<CC, 256>>>(p_c1, gamma, beta, p_sc, p_sh);
    prepw_kernel<4096><<<(512*2048 + 255)/256, 256>>>(w2, p_w2b);
    conv_tc_kernel<8,4,4096,8200,260><<<dim3(32, 4, BB), 256, SM_L2>>>(
        p_apb, p_w2b, p_c2, L2);

    init_kernel<<<16, 256>>>(hidden);
    prepw_kernel<2048><<<(512*1024 + 255)/256, 256>>>(w345 + 0*512*2048, p_w345b + 0*655360);
    prepw_kernel<2048><<<(512*1024 + 255)/256, 256>>>(w345 + 1*512*2048, p_w345b + 1*655360);
    prepw_kernel<2048><<<(512*1024 + 255)/256, 256>>>(w345 + 2*512*2048, p_w345b + 2*655360);

    statsprep_kernel<L2,2064,1><<<CC, 256>>>(p_c2, gamma + CC, beta + CC, p_sc + CC, p_sh + CC);
    conv_tc_kernel<4,2,2048,2064,144><<<dim3(16, 4, BB), 256, SM_L345>>>(
        p_apb, p_w345b + 0*655360, p_c3, L3);

    statsprep_kernel<L3,1040,1><<<CC, 256>>>(p_c3, gamma + 2*CC, beta + 2*CC, p_sc + 2*CC, p_sh + 2*CC);
    conv_tc_kernel<4,2,2048,1040,144><<<dim3(8, 4, BB), 256, SM_L345>>>(
        p_apb, p_w345b + 1*655360, p_c4, L4);

    statsprep_kernel<L4,528,1><<<CC, 256>>>(p_c4, gamma + 3*CC, beta + 3*CC, p_sc + 3*CC, p_sh + 3*CC);
    conv_tc_kernel<4,2,2048,528,144><<<dim3(4, 4, BB), 256, SM_L345>>>(
        p_apb, p_w345b + 2*655360, p_c5, L5);

    stats_kernel<<<CC, 256>>>(p_c5, gamma + 4*CC, beta + 4*CC, p_sc + 4*CC, p_sh + 4*CC, L5);

    buildz_kernel<<<dim3(TT, BB), CC>>>(tsamp, p_sc + 4*CC, p_sh + 4*CC);
    gi_gemm_kernel<<<dim3(125, 12), 256>>>(wih);
    gruclu_kernel<<<8, 256, SM_GRU>>>(whh, bih, bhh, tsamp);

    enc_kernel<<<dim3(KCPC, BB), CC>>>(tsamp, p_sc + 4*CC, p_sh + 4*CC);
    pred_kernel<<<dim3(KCPC, BB), CC>>>(wk, wkb);
    total_kernel<<<KCPC, 256>>>();
    final_kernel<<<1, 256>>>(out);
}